// round 12
// baseline (speedup 1.0000x reference)
#include <cuda_runtime.h>
#include <cuda_bf16.h>
#include <cstdint>
#include <math.h>

// Problem constants
#define B_ 4
#define T_ 2048
#define C_ 1024
#define H_ 16
#define D_ 64
#define M_ (B_ * T_)          // 8192 rows
#define QKV_N (3 * C_)        // 3072

// softmax runs in exp2 domain: q pre-scaled by 1/sqrt(D) * log2(e)
#define QSCALE 0.18033688011112042f

// Scratch (tf32 bit patterns in f32 containers, except final output)
__device__ float g_qkv[(size_t)M_ * QKV_N];
__device__ float g_ctx[(size_t)M_ * C_];
__device__ float g_xc[(size_t)M_ * C_];
__device__ float g_w1[(size_t)QKV_N * C_];
__device__ float g_w2[(size_t)C_ * C_];

// ===========================================================================
// helpers
// ===========================================================================
__device__ __forceinline__ uint32_t smem_u32(const void* p) {
    uint32_t a;
    asm("{ .reg .u64 t; cvta.to.shared.u64 t, %1; cvt.u32.u64 %0, t; }"
        : "=r"(a) : "l"(p));
    return a;
}

__device__ __forceinline__ void cp16(uint32_t dst, const void* src) {
    asm volatile("cp.async.cg.shared.global [%0], [%1], 16;"
        :: "r"(dst), "l"(src) : "memory");
}
#define CP_COMMIT() asm volatile("cp.async.commit_group;" ::: "memory")

__device__ __forceinline__ uint32_t f2tf32(float v) {
    uint32_t r;
    asm("cvt.rna.tf32.f32 %0, %1;" : "=r"(r) : "f"(v));
    return r;
}
__device__ __forceinline__ float tf32f(float v) {
    return __uint_as_float(f2tf32(v));
}

__device__ __forceinline__ float fexp2(float x) {
    float y;
    asm("ex2.approx.f32 %0, %1;" : "=f"(y) : "f"(x));
    return y;
}

__device__ __forceinline__ void mma_tf32(
    float& c0, float& c1, float& c2, float& c3,
    uint32_t a0, uint32_t a1, uint32_t a2, uint32_t a3,
    uint32_t b0, uint32_t b1)
{
    asm volatile(
        "mma.sync.aligned.m16n8k8.row.col.f32.tf32.tf32.f32 "
        "{%0,%1,%2,%3}, {%4,%5,%6,%7}, {%8,%9}, {%0,%1,%2,%3};"
        : "+f"(c0), "+f"(c1), "+f"(c2), "+f"(c3)
        : "r"(a0), "r"(a1), "r"(a2), "r"(a3), "r"(b0), "r"(b1));
}

// ===========================================================================
// fused tf32 pre-conversion of x, qkv_w, out_w (one launch)
// ===========================================================================
#define N4_X  (M_ * C_ / 4)
#define N4_W1 (QKV_N * C_ / 4)
#define N4_W2 (C_ * C_ / 4)
#define N4_ALL (N4_X + N4_W1 + N4_W2)

__global__ void __launch_bounds__(256) cvt_tf32_all(
    const float4* __restrict__ x,  float4* __restrict__ xo,
    const float4* __restrict__ w1, float4* __restrict__ w1o,
    const float4* __restrict__ w2, float4* __restrict__ w2o)
{
    int i = blockIdx.x * blockDim.x + threadIdx.x;
    const float4* src;
    float4* dst;
    int k;
    if (i < N4_X)              { src = x;  dst = xo;  k = i; }
    else if (i < N4_X + N4_W1) { src = w1; dst = w1o; k = i - N4_X; }
    else if (i < N4_ALL)       { src = w2; dst = w2o; k = i - N4_X - N4_W1; }
    else return;
    float4 v = src[k];
    v.x = tf32f(v.x); v.y = tf32f(v.y);
    v.z = tf32f(v.z); v.w = tf32f(v.w);
    dst[k] = v;
}

// ===========================================================================
// tf32 mma.sync NT GEMM — round-10 config (verified best).
// CTA 128x128x32, 256 threads, warp tile 64x32, XOR-swizzled smem,
// 3-stage cp.async, one sync per iter, 2 CTAs/SM.
// CVT_OUT epilogue additionally scales q columns (n0 < C_) by QSCALE.
// ===========================================================================
#define BM 128
#define BN 128
#define BK 32
#define STGW (BM * BK)                   // 4096 words per matrix per stage
#define NSTG 3
#define GEMM_SMEM (NSTG * 2 * STGW * 4)  // 98304 bytes

template<bool CVT_OUT>
__global__ void __launch_bounds__(256, 2) gemm_mma_kernel(
    const float* __restrict__ A, const float* __restrict__ W,
    const float* __restrict__ bias, float* __restrict__ Cmat,
    int M, int N, int K)
{
    extern __shared__ __align__(16) float smf[];
    const uint32_t sb = smem_u32(smf);

    const int tid  = threadIdx.x;
    const int lane = tid & 31;
    const int wid  = tid >> 5;
    const int wm   = (wid & 1) * 64;
    const int wn   = (wid >> 1) * 32;
    const int g    = lane >> 2;
    const int tg   = lane & 3;

    const int m0 = blockIdx.y * BM;
    const int n0 = blockIdx.x * BN;
    const int NK = K / BK;

    const float* Abase = A + (size_t)m0 * K;
    const float* Wbase = W + (size_t)n0 * K;

    const int xg = (g & 3) << 1;
    int koff[4];
    #pragma unroll
    for (int ks = 0; ks < 4; ks++)
        koff[ks] = (((2 * ks + (tg >> 1)) ^ xg) << 2) + ((tg & 1) << 1);

    auto load_stage = [&](int kc) {
        const int st = kc % NSTG;
        const uint32_t sA = sb + (uint32_t)st * 2 * STGW * 4;
        const uint32_t sB = sA + STGW * 4;
        const int kOff = kc * BK;
        #pragma unroll
        for (int t = 0; t < 4; t++) {
            int idx = tid + t * 256;
            int r = idx >> 3;
            int c = idx & 7;
            uint32_t off =
                (uint32_t)(r * 32 + ((c ^ ((r & 3) << 1)) << 2)) * 4;
            cp16(sA + off, Abase + (size_t)r * K + kOff + c * 4);
            cp16(sB + off, Wbase + (size_t)r * K + kOff + c * 4);
        }
        CP_COMMIT();
    };

    float acc[4][4][4] = {};

    load_stage(0);
    if (NK > 1) load_stage(1);

    for (int kc = 0; kc < NK; kc++) {
        if (kc + 1 < NK) asm volatile("cp.async.wait_group 1;" ::: "memory");
        else             asm volatile("cp.async.wait_group 0;" ::: "memory");
        __syncthreads();

        const int st = kc % NSTG;
        const float* As = smf + st * 2 * STGW;
        const float* Bs = As + STGW;

        #pragma unroll
        for (int ks = 0; ks < 4; ks++) {
            uint32_t af[4][4], bf[4][2];
            #pragma unroll
            for (int i = 0; i < 4; i++) {
                const float* ap = As + (wm + i * 16 + g) * 32 + koff[ks];
                float2 lo = *(const float2*)ap;
                float2 hi = *(const float2*)(ap + 8 * 32);
                af[i][0] = __float_as_uint(lo.x);
                af[i][2] = __float_as_uint(lo.y);
                af[i][1] = __float_as_uint(hi.x);
                af[i][3] = __float_as_uint(hi.y);
            }
            #pragma unroll
            for (int j = 0; j < 4; j++) {
                float2 bb = *(const float2*)
                    (Bs + (wn + j * 8 + g) * 32 + koff[ks]);
                bf[j][0] = __float_as_uint(bb.x);
                bf[j][1] = __float_as_uint(bb.y);
            }
            #pragma unroll
            for (int i = 0; i < 4; i++)
                #pragma unroll
                for (int j = 0; j < 4; j++)
                    mma_tf32(acc[i][j][0], acc[i][j][1],
                             acc[i][j][2], acc[i][j][3],
                             af[i][0], af[i][1], af[i][2], af[i][3],
                             bf[j][0], bf[j][1]);
        }

        if (kc + 2 < NK) load_stage(kc + 2);
    }

    // q columns (n0 < C_) of the QKV output get the softmax scale folded in
    const float qs = (CVT_OUT && n0 < C_) ? QSCALE : 1.0f;

    #pragma unroll
    for (int i = 0; i < 4; i++) {
        const int row = m0 + wm + i * 16 + g;
        #pragma unroll
        for (int j = 0; j < 4; j++) {
            const int col = n0 + wn + j * 8 + tg * 2;
            float b0 = __ldg(bias + col);
            float b1 = __ldg(bias + col + 1);
            float2 v0, v1;
            if (CVT_OUT) {
                v0 = make_float2(tf32f((acc[i][j][0] + b0) * qs),
                                 tf32f((acc[i][j][1] + b1) * qs));
                v1 = make_float2(tf32f((acc[i][j][2] + b0) * qs),
                                 tf32f((acc[i][j][3] + b1) * qs));
            } else {
                v0 = make_float2(acc[i][j][0] + b0, acc[i][j][1] + b1);
                v1 = make_float2(acc[i][j][2] + b0, acc[i][j][3] + b1);
            }
            *(float2*)&Cmat[(size_t)row * N + col] = v0;
            *(float2*)&Cmat[(size_t)(row + 8) * N + col] = v1;
        }
    }
}

// ===========================================================================
// Tensor-core flash attention (tf32, causal) — round-9/10 shape (QB=128,
// 128 threads = 4 warps x 32 q-rows, 2 CTAs/SM) with a slimmer softmax:
//   - q pre-scaled by QSCALE in the GEMM -> exp2-domain, no scale FMULs
//   - ex2.approx directly (half the exp instructions of __expf)
//   - P fragments fed to the mma as raw fp32 bits (tf32 HMMA reads the
//     top 19 bits; truncation instead of cvt.rna -> 64 fewer cvts/iter)
//   - diagonal tiles skip fully-masked j-tiles (jhi) in QK^T, exp and PV
// ===========================================================================
#define QB 128
#define QLD 72
#define KLD 72
#define VLD 68
#define K_TILE (64 * KLD)
#define V_TILE (64 * VLD)
#define Q_FLOATS (QB * QLD)
#define KS_BASE  Q_FLOATS
#define VS_BASE  (Q_FLOATS + 2 * K_TILE)
#define ATT_SMEM ((VS_BASE + 2 * V_TILE) * 4)    // 108544 B

__global__ void __launch_bounds__(128, 2) attn_tc_kernel(
    const float* __restrict__ qkv, float* __restrict__ ctx)
{
    extern __shared__ __align__(16) float sm[];
    float* Qs = sm;
    const uint32_t sb = smem_u32(sm);

    const int tid  = threadIdx.x;
    const int lane = tid & 31;
    const int wid  = tid >> 5;
    const int g    = lane >> 2;
    const int tg   = lane & 3;
    const int wm   = wid * 32;

    const int bh = blockIdx.x;
    const int b  = bh >> 4;
    const int h  = bh & 15;
    const int qblock = 15 - (int)blockIdx.y;
    const int q0 = qblock << 7;
    const int nk = (qblock + 1) * 2;

    const size_t base = (size_t)b * T_ * QKV_N + (size_t)h * D_;

    auto load_k = [&](int fbase, const float* gsrc) {
        #pragma unroll
        for (int t = 0; t < 8; t++) {
            int idx = tid + t * 128;
            int r = idx >> 4;
            int c4 = (idx & 15) << 2;
            cp16(sb + (uint32_t)(fbase + r * KLD + c4) * 4,
                 gsrc + (size_t)r * QKV_N + c4);
        }
    };
    auto load_v = [&](int fbase, const float* gsrc) {
        #pragma unroll
        for (int t = 0; t < 8; t++) {
            int idx = tid + t * 128;
            int r = idx >> 4;
            int c4 = (idx & 15) << 2;
            cp16(sb + (uint32_t)(fbase + r * VLD + c4) * 4,
                 gsrc + (size_t)r * QKV_N + c4);
        }
    };

    {
        const float* qsrc = qkv + base + (size_t)q0 * QKV_N;
        #pragma unroll
        for (int t = 0; t < 16; t++) {
            int idx = tid + t * 128;
            int r = idx >> 4;
            int c4 = (idx & 15) << 2;
            cp16(sb + (uint32_t)(r * QLD + c4) * 4,
                 qsrc + (size_t)r * QKV_N + c4);
        }
        load_k(KS_BASE, qkv + base + C_);
        load_v(VS_BASE, qkv + base + 2 * C_);
        CP_COMMIT();
        load_k(KS_BASE + K_TILE, qkv + base + (size_t)64 * QKV_N + C_);
        load_v(VS_BASE + V_TILE, qkv + base + (size_t)64 * QKV_N + 2 * C_);
        CP_COMMIT();
    }
    asm volatile("cp.async.wait_group 1;" ::: "memory");
    __syncthreads();

    float o[2][8][4] = {};
    float mi[2][2] = {{-1e30f, -1e30f}, {-1e30f, -1e30f}};
    float li[2][2] = {};

    // one k-tile of work; jhi = number of live j-tiles, dg = apply mask
    auto compute_tile = [&](const float* Kb, const float* Vb,
                            int k0, int jhi, bool dg) {
        // ---- S = Q K^T (exp2-domain scores; q pre-scaled) ----
        float s[2][8][4] = {};
        #pragma unroll
        for (int ks = 0; ks < 8; ks++) {
            const int kk = ks * 8;
            uint32_t af[2][4];
            #pragma unroll
            for (int m2 = 0; m2 < 2; m2++) {
                const float* qp =
                    Qs + (wm + m2 * 16 + g) * QLD + kk + tg * 2;
                float2 qa = *(const float2*)qp;
                float2 qb = *(const float2*)(qp + 8 * QLD);
                af[m2][0] = __float_as_uint(qa.x);
                af[m2][2] = __float_as_uint(qa.y);
                af[m2][1] = __float_as_uint(qb.x);
                af[m2][3] = __float_as_uint(qb.y);
            }
            #pragma unroll 8
            for (int j = 0; j < jhi; j++) {
                float2 kb2 = *(const float2*)
                    (Kb + (j * 8 + g) * KLD + kk + tg * 2);
                uint32_t b0 = __float_as_uint(kb2.x);
                uint32_t b1 = __float_as_uint(kb2.y);
                #pragma unroll
                for (int m2 = 0; m2 < 2; m2++)
                    mma_tf32(s[m2][j][0], s[m2][j][1],
                             s[m2][j][2], s[m2][j][3],
                             af[m2][0], af[m2][1], af[m2][2], af[m2][3],
                             b0, b1);
            }
        }

        // ---- mask + online softmax (exp2-domain) ----
        #pragma unroll
        for (int m2 = 0; m2 < 2; m2++) {
            #pragma unroll
            for (int h2 = 0; h2 < 2; h2++) {
                const int rowg = q0 + wm + m2 * 16 + g + h2 * 8;
                float mx = -1e30f;
                #pragma unroll 8
                for (int j = 0; j < jhi; j++) {
                    float v0 = s[m2][j][h2 * 2 + 0];
                    float v1 = s[m2][j][h2 * 2 + 1];
                    if (dg) {
                        int col = k0 + j * 8 + tg * 2;
                        if (col > rowg)     v0 = -1e30f;
                        if (col + 1 > rowg) v1 = -1e30f;
                    }
                    s[m2][j][h2 * 2 + 0] = v0;
                    s[m2][j][h2 * 2 + 1] = v1;
                    mx = fmaxf(mx, fmaxf(v0, v1));
                }
                mx = fmaxf(mx, __shfl_xor_sync(0xffffffffu, mx, 1));
                mx = fmaxf(mx, __shfl_xor_sync(0xffffffffu, mx, 2));

                float mnew = fmaxf(mi[m2][h2], mx);
                float alpha = fexp2(mi[m2][h2] - mnew);
                float rs = 0.0f;
                #pragma unroll 8
                for (int j = 0; j < jhi; j++) {
                    float p0 = fexp2(s[m2][j][h2 * 2 + 0] - mnew);
                    float p1 = fexp2(s[m2][j][h2 * 2 + 1] - mnew);
                    s[m2][j][h2 * 2 + 0] = p0;
                    s[m2][j][h2 * 2 + 1] = p1;
                    rs += p0 + p1;
                }
                rs += __shfl_xor_sync(0xffffffffu, rs, 1);
                rs += __shfl_xor_sync(0xffffffffu, rs, 2);
                li[m2][h2] = li[m2][h2] * alpha + rs;
                mi[m2][h2] = mnew;
                #pragma unroll
                for (int n = 0; n < 8; n++) {
                    o[m2][n][h2 * 2 + 0] *= alpha;
                    o[m2][n][h2 * 2 + 1] *= alpha;
                }
            }
        }

        // ---- O += P V (P as raw fp32 bits: HW tf32 truncation) ----
        #pragma unroll 8
        for (int j = 0; j < jhi; j++) {
            uint32_t a[2][4];
            #pragma unroll
            for (int m2 = 0; m2 < 2; m2++) {
                a[m2][0] = __float_as_uint(s[m2][j][0]);
                a[m2][1] = __float_as_uint(s[m2][j][2]);
                a[m2][2] = __float_as_uint(s[m2][j][1]);
                a[m2][3] = __float_as_uint(s[m2][j][3]);
            }
            #pragma unroll
            for (int n = 0; n < 8; n++) {
                uint32_t b0 = __float_as_uint(
                    Vb[(j * 8 + tg * 2) * VLD + n * 8 + g]);
                uint32_t b1 = __float_as_uint(
                    Vb[(j * 8 + tg * 2 + 1) * VLD + n * 8 + g]);
                #pragma unroll
                for (int m2 = 0; m2 < 2; m2++)
                    mma_tf32(o[m2][n][0], o[m2][n][1],
                             o[m2][n][2], o[m2][n][3],
                             a[m2][0], a[m2][1], a[m2][2], a[m2][3],
                             b0, b1);
            }
        }
    };

    for (int it = 0; it < nk; it++) {
        const int cur = it & 1;
        const int k0 = it * 64;
        const float* Kb = sm + KS_BASE + cur * K_TILE;
        const float* Vb = sm + VS_BASE + cur * V_TILE;

        if (k0 <= q0 + wm + 31) {
            if (k0 + 63 <= q0 + wm) {
                compute_tile(Kb, Vb, k0, 8, false);     // fully unmasked
            } else {
                int jhi = ((q0 + wm + 31 - k0) >> 3) + 1;
                compute_tile(Kb, Vb, k0, jhi, true);    // diagonal
            }
        }
        __syncthreads();

        if (it + 2 < nk) {
            const size_t roff = base + (size_t)(it + 2) * 64 * QKV_N;
            load_k(KS_BASE + cur * K_TILE, qkv + roff + C_);
            load_v(VS_BASE + cur * V_TILE, qkv + roff + 2 * C_);
            CP_COMMIT();
        }
        if (it + 1 < nk) {
            if (it + 2 < nk) asm volatile("cp.async.wait_group 1;" ::: "memory");
            else             asm volatile("cp.async.wait_group 0;" ::: "memory");
            __syncthreads();
        }
    }

    // ---- epilogue: tf32-rounded ctx (feeds tf32 out-proj) ----
    #pragma unroll
    for (int m2 = 0; m2 < 2; m2++) {
        #pragma unroll
        for (int h2 = 0; h2 < 2; h2++) {
            const float inv = 1.0f / li[m2][h2];
            const size_t row =
                (size_t)(b * T_ + q0 + wm + m2 * 16 + g + h2 * 8);
            #pragma unroll
            for (int n = 0; n < 8; n++) {
                float2 v = make_float2(tf32f(o[m2][n][h2 * 2 + 0] * inv),
                                       tf32f(o[m2][n][h2 * 2 + 1] * inv));
                *(float2*)&ctx[row * C_ + h * D_ + n * 8 + tg * 2] = v;
            }
        }
    }
}

// ---------------------------------------------------------------------------
// Launch
// ---------------------------------------------------------------------------
extern "C" void kernel_launch(void* const* d_in, const int* in_sizes, int n_in,
                              void* d_out, int out_size)
{
    const float* x      = (const float*)d_in[0];
    const float* qkv_w  = (const float*)d_in[1];
    const float* qkv_b  = (const float*)d_in[2];
    const float* out_w  = (const float*)d_in[3];
    const float* out_b  = (const float*)d_in[4];
    float* out = (float*)d_out;

    float *qkv_ptr, *ctx_ptr, *xc_ptr, *w1_ptr, *w2_ptr;
    cudaGetSymbolAddress((void**)&qkv_ptr, g_qkv);
    cudaGetSymbolAddress((void**)&ctx_ptr, g_ctx);
    cudaGetSymbolAddress((void**)&xc_ptr, g_xc);
    cudaGetSymbolAddress((void**)&w1_ptr, g_w1);
    cudaGetSymbolAddress((void**)&w2_ptr, g_w2);

    cudaFuncSetAttribute(gemm_mma_kernel<true>,
                         cudaFuncAttributeMaxDynamicSharedMemorySize, GEMM_SMEM);
    cudaFuncSetAttribute(gemm_mma_kernel<false>,
                         cudaFuncAttributeMaxDynamicSharedMemorySize, GEMM_SMEM);
    cudaFuncSetAttribute(attn_tc_kernel,
                         cudaFuncAttributeMaxDynamicSharedMemorySize, ATT_SMEM);

    // 0) fused tf32 pre-conversion
    cvt_tf32_all<<<(N4_ALL + 255) / 256, 256>>>(
        (const float4*)x, (float4*)xc_ptr,
        (const float4*)qkv_w, (float4*)w1_ptr,
        (const float4*)out_w, (float4*)w2_ptr);

    // 1) QKV projection (q columns pre-scaled by QSCALE)
    gemm_mma_kernel<true><<<dim3(QKV_N / BN, M_ / BM), 256, GEMM_SMEM>>>(
        xc_ptr, w1_ptr, qkv_b, qkv_ptr, M_, QKV_N, C_);

    // 2) causal flash attention (exp2-domain softmax)
    attn_tc_kernel<<<dim3(H_ * B_, T_ / QB), 128, ATT_SMEM>>>(qkv_ptr, ctx_ptr);

    // 3) output projection
    gemm_mma_kernel<false><<<dim3(C_ / BN, M_ / BM), 256, GEMM_SMEM>>>(
        ctx_ptr, w2_ptr, out_b, out, M_, C_, C_);
}

// round 13
// speedup vs baseline: 1.1239x; 1.1239x over previous
#include <cuda_runtime.h>
#include <cuda_bf16.h>
#include <cstdint>
#include <math.h>

// Problem constants
#define B_ 4
#define T_ 2048
#define C_ 1024
#define H_ 16
#define D_ 64
#define M_ (B_ * T_)          // 8192 rows
#define QKV_N (3 * C_)        // 3072

// softmax runs in exp2 domain: q pre-scaled by 1/sqrt(D) * log2(e)
#define QSCALE 0.18033688011112042f

// Scratch (tf32 bit patterns in f32 containers, except final output)
__device__ float g_qkv[(size_t)M_ * QKV_N];
__device__ float g_ctx[(size_t)M_ * C_];
__device__ float g_xc[(size_t)M_ * C_];
__device__ float g_w1[(size_t)QKV_N * C_];
__device__ float g_w2[(size_t)C_ * C_];

// ===========================================================================
// helpers
// ===========================================================================
__device__ __forceinline__ uint32_t smem_u32(const void* p) {
    uint32_t a;
    asm("{ .reg .u64 t; cvta.to.shared.u64 t, %1; cvt.u32.u64 %0, t; }"
        : "=r"(a) : "l"(p));
    return a;
}

__device__ __forceinline__ void cp16(uint32_t dst, const void* src) {
    asm volatile("cp.async.cg.shared.global [%0], [%1], 16;"
        :: "r"(dst), "l"(src) : "memory");
}
#define CP_COMMIT() asm volatile("cp.async.commit_group;" ::: "memory")

__device__ __forceinline__ uint32_t f2tf32(float v) {
    uint32_t r;
    asm("cvt.rna.tf32.f32 %0, %1;" : "=r"(r) : "f"(v));
    return r;
}
__device__ __forceinline__ float tf32f(float v) {
    return __uint_as_float(f2tf32(v));
}

__device__ __forceinline__ float fexp2(float x) {
    float y;
    asm("ex2.approx.f32 %0, %1;" : "=f"(y) : "f"(x));
    return y;
}

__device__ __forceinline__ void mma_tf32(
    float& c0, float& c1, float& c2, float& c3,
    uint32_t a0, uint32_t a1, uint32_t a2, uint32_t a3,
    uint32_t b0, uint32_t b1)
{
    asm volatile(
        "mma.sync.aligned.m16n8k8.row.col.f32.tf32.tf32.f32 "
        "{%0,%1,%2,%3}, {%4,%5,%6,%7}, {%8,%9}, {%0,%1,%2,%3};"
        : "+f"(c0), "+f"(c1), "+f"(c2), "+f"(c3)
        : "r"(a0), "r"(a1), "r"(a2), "r"(a3), "r"(b0), "r"(b1));
}

// ===========================================================================
// fused tf32 pre-conversion of x, qkv_w, out_w (one launch)
// ===========================================================================
#define N4_X  (M_ * C_ / 4)
#define N4_W1 (QKV_N * C_ / 4)
#define N4_W2 (C_ * C_ / 4)
#define N4_ALL (N4_X + N4_W1 + N4_W2)

__global__ void __launch_bounds__(256) cvt_tf32_all(
    const float4* __restrict__ x,  float4* __restrict__ xo,
    const float4* __restrict__ w1, float4* __restrict__ w1o,
    const float4* __restrict__ w2, float4* __restrict__ w2o)
{
    int i = blockIdx.x * blockDim.x + threadIdx.x;
    const float4* src;
    float4* dst;
    int k;
    if (i < N4_X)              { src = x;  dst = xo;  k = i; }
    else if (i < N4_X + N4_W1) { src = w1; dst = w1o; k = i - N4_X; }
    else if (i < N4_ALL)       { src = w2; dst = w2o; k = i - N4_X - N4_W1; }
    else return;
    float4 v = src[k];
    v.x = tf32f(v.x); v.y = tf32f(v.y);
    v.z = tf32f(v.z); v.w = tf32f(v.w);
    dst[k] = v;
}

// ===========================================================================
// tf32 mma.sync NT GEMM — round-10 config (verified best).
// CTA 128x128x32, 256 threads, warp tile 64x32, XOR-swizzled smem,
// 3-stage cp.async, one sync per iter, 2 CTAs/SM.
// CVT_OUT epilogue additionally scales q columns (n0 < C_) by QSCALE.
// ===========================================================================
#define BM 128
#define BN 128
#define BK 32
#define STGW (BM * BK)                   // 4096 words per matrix per stage
#define NSTG 3
#define GEMM_SMEM (NSTG * 2 * STGW * 4)  // 98304 bytes

template<bool CVT_OUT>
__global__ void __launch_bounds__(256, 2) gemm_mma_kernel(
    const float* __restrict__ A, const float* __restrict__ W,
    const float* __restrict__ bias, float* __restrict__ Cmat,
    int M, int N, int K)
{
    extern __shared__ __align__(16) float smf[];
    const uint32_t sb = smem_u32(smf);

    const int tid  = threadIdx.x;
    const int lane = tid & 31;
    const int wid  = tid >> 5;
    const int wm   = (wid & 1) * 64;
    const int wn   = (wid >> 1) * 32;
    const int g    = lane >> 2;
    const int tg   = lane & 3;

    const int m0 = blockIdx.y * BM;
    const int n0 = blockIdx.x * BN;
    const int NK = K / BK;

    const float* Abase = A + (size_t)m0 * K;
    const float* Wbase = W + (size_t)n0 * K;

    const int xg = (g & 3) << 1;
    int koff[4];
    #pragma unroll
    for (int ks = 0; ks < 4; ks++)
        koff[ks] = (((2 * ks + (tg >> 1)) ^ xg) << 2) + ((tg & 1) << 1);

    auto load_stage = [&](int kc) {
        const int st = kc % NSTG;
        const uint32_t sA = sb + (uint32_t)st * 2 * STGW * 4;
        const uint32_t sB = sA + STGW * 4;
        const int kOff = kc * BK;
        #pragma unroll
        for (int t = 0; t < 4; t++) {
            int idx = tid + t * 256;
            int r = idx >> 3;
            int c = idx & 7;
            uint32_t off =
                (uint32_t)(r * 32 + ((c ^ ((r & 3) << 1)) << 2)) * 4;
            cp16(sA + off, Abase + (size_t)r * K + kOff + c * 4);
            cp16(sB + off, Wbase + (size_t)r * K + kOff + c * 4);
        }
        CP_COMMIT();
    };

    float acc[4][4][4] = {};

    load_stage(0);
    if (NK > 1) load_stage(1);

    for (int kc = 0; kc < NK; kc++) {
        if (kc + 1 < NK) asm volatile("cp.async.wait_group 1;" ::: "memory");
        else             asm volatile("cp.async.wait_group 0;" ::: "memory");
        __syncthreads();

        const int st = kc % NSTG;
        const float* As = smf + st * 2 * STGW;
        const float* Bs = As + STGW;

        #pragma unroll
        for (int ks = 0; ks < 4; ks++) {
            uint32_t af[4][4], bf[4][2];
            #pragma unroll
            for (int i = 0; i < 4; i++) {
                const float* ap = As + (wm + i * 16 + g) * 32 + koff[ks];
                float2 lo = *(const float2*)ap;
                float2 hi = *(const float2*)(ap + 8 * 32);
                af[i][0] = __float_as_uint(lo.x);
                af[i][2] = __float_as_uint(lo.y);
                af[i][1] = __float_as_uint(hi.x);
                af[i][3] = __float_as_uint(hi.y);
            }
            #pragma unroll
            for (int j = 0; j < 4; j++) {
                float2 bb = *(const float2*)
                    (Bs + (wn + j * 8 + g) * 32 + koff[ks]);
                bf[j][0] = __float_as_uint(bb.x);
                bf[j][1] = __float_as_uint(bb.y);
            }
            #pragma unroll
            for (int i = 0; i < 4; i++)
                #pragma unroll
                for (int j = 0; j < 4; j++)
                    mma_tf32(acc[i][j][0], acc[i][j][1],
                             acc[i][j][2], acc[i][j][3],
                             af[i][0], af[i][1], af[i][2], af[i][3],
                             bf[j][0], bf[j][1]);
        }

        if (kc + 2 < NK) load_stage(kc + 2);
    }

    // q columns (n0 < C_) of the QKV output get the softmax scale folded in
    const float qs = (CVT_OUT && n0 < C_) ? QSCALE : 1.0f;

    #pragma unroll
    for (int i = 0; i < 4; i++) {
        const int row = m0 + wm + i * 16 + g;
        #pragma unroll
        for (int j = 0; j < 4; j++) {
            const int col = n0 + wn + j * 8 + tg * 2;
            float b0 = __ldg(bias + col);
            float b1 = __ldg(bias + col + 1);
            float2 v0, v1;
            if (CVT_OUT) {
                v0 = make_float2(tf32f((acc[i][j][0] + b0) * qs),
                                 tf32f((acc[i][j][1] + b1) * qs));
                v1 = make_float2(tf32f((acc[i][j][2] + b0) * qs),
                                 tf32f((acc[i][j][3] + b1) * qs));
            } else {
                v0 = make_float2(acc[i][j][0] + b0, acc[i][j][1] + b1);
                v1 = make_float2(acc[i][j][2] + b0, acc[i][j][3] + b1);
            }
            *(float2*)&Cmat[(size_t)row * N + col] = v0;
            *(float2*)&Cmat[(size_t)(row + 8) * N + col] = v1;
        }
    }
}

// ===========================================================================
// Tensor-core flash attention (tf32, causal) — round-10 structure VERBATIM
// (QB=128, 128 threads = 4 warps x 32 q-rows, 2 CTAs/SM, constant loop
// bounds), with only straight-line softmax cuts:
//   - q pre-scaled by QSCALE in the GEMM -> exp2 domain, no scale FMULs
//   - ex2.approx.f32 instead of __expf
//   - P fragments as raw fp32 bits (HW tf32 truncation, no cvt.rna)
// ===========================================================================
#define QB 128
#define QLD 72
#define KLD 72
#define VLD 68
#define K_TILE (64 * KLD)
#define V_TILE (64 * VLD)
#define Q_FLOATS (QB * QLD)
#define KS_BASE  Q_FLOATS
#define VS_BASE  (Q_FLOATS + 2 * K_TILE)
#define ATT_SMEM ((VS_BASE + 2 * V_TILE) * 4)    // 108544 B

__global__ void __launch_bounds__(128, 2) attn_tc_kernel(
    const float* __restrict__ qkv, float* __restrict__ ctx)
{
    extern __shared__ __align__(16) float sm[];
    float* Qs = sm;
    const uint32_t sb = smem_u32(sm);

    const int tid  = threadIdx.x;
    const int lane = tid & 31;
    const int wid  = tid >> 5;
    const int g    = lane >> 2;
    const int tg   = lane & 3;
    const int wm   = wid * 32;

    const int bh = blockIdx.x;
    const int b  = bh >> 4;
    const int h  = bh & 15;
    const int qblock = 15 - (int)blockIdx.y;
    const int q0 = qblock << 7;
    const int nk = (qblock + 1) * 2;

    const size_t base = (size_t)b * T_ * QKV_N + (size_t)h * D_;

    auto load_k = [&](int fbase, const float* gsrc) {
        #pragma unroll
        for (int t = 0; t < 8; t++) {
            int idx = tid + t * 128;
            int r = idx >> 4;
            int c4 = (idx & 15) << 2;
            cp16(sb + (uint32_t)(fbase + r * KLD + c4) * 4,
                 gsrc + (size_t)r * QKV_N + c4);
        }
    };
    auto load_v = [&](int fbase, const float* gsrc) {
        #pragma unroll
        for (int t = 0; t < 8; t++) {
            int idx = tid + t * 128;
            int r = idx >> 4;
            int c4 = (idx & 15) << 2;
            cp16(sb + (uint32_t)(fbase + r * VLD + c4) * 4,
                 gsrc + (size_t)r * QKV_N + c4);
        }
    };

    {
        const float* qsrc = qkv + base + (size_t)q0 * QKV_N;
        #pragma unroll
        for (int t = 0; t < 16; t++) {
            int idx = tid + t * 128;
            int r = idx >> 4;
            int c4 = (idx & 15) << 2;
            cp16(sb + (uint32_t)(r * QLD + c4) * 4,
                 qsrc + (size_t)r * QKV_N + c4);
        }
        load_k(KS_BASE, qkv + base + C_);
        load_v(VS_BASE, qkv + base + 2 * C_);
        CP_COMMIT();
        load_k(KS_BASE + K_TILE, qkv + base + (size_t)64 * QKV_N + C_);
        load_v(VS_BASE + V_TILE, qkv + base + (size_t)64 * QKV_N + 2 * C_);
        CP_COMMIT();
    }
    asm volatile("cp.async.wait_group 1;" ::: "memory");
    __syncthreads();

    float o[2][8][4] = {};
    float mi[2][2] = {{-1e30f, -1e30f}, {-1e30f, -1e30f}};
    float li[2][2] = {};

    for (int it = 0; it < nk; it++) {
        const int cur = it & 1;
        const int k0 = it * 64;
        const float* Kb = sm + KS_BASE + cur * K_TILE;
        const float* Vb = sm + VS_BASE + cur * V_TILE;

        if (k0 <= q0 + wm + 31) {
            // ---- S = Q K^T (exp2-domain scores; q pre-scaled) ----
            float s[2][8][4] = {};
            #pragma unroll
            for (int ks = 0; ks < 8; ks++) {
                const int kk = ks * 8;
                uint32_t af[2][4];
                #pragma unroll
                for (int m2 = 0; m2 < 2; m2++) {
                    const float* qp =
                        Qs + (wm + m2 * 16 + g) * QLD + kk + tg * 2;
                    float2 qa = *(const float2*)qp;
                    float2 qb = *(const float2*)(qp + 8 * QLD);
                    af[m2][0] = __float_as_uint(qa.x);
                    af[m2][2] = __float_as_uint(qa.y);
                    af[m2][1] = __float_as_uint(qb.x);
                    af[m2][3] = __float_as_uint(qb.y);
                }
                #pragma unroll
                for (int j = 0; j < 8; j++) {
                    float2 kb2 = *(const float2*)
                        (Kb + (j * 8 + g) * KLD + kk + tg * 2);
                    uint32_t b0 = __float_as_uint(kb2.x);
                    uint32_t b1 = __float_as_uint(kb2.y);
                    #pragma unroll
                    for (int m2 = 0; m2 < 2; m2++)
                        mma_tf32(s[m2][j][0], s[m2][j][1],
                                 s[m2][j][2], s[m2][j][3],
                                 af[m2][0], af[m2][1], af[m2][2], af[m2][3],
                                 b0, b1);
                }
            }

            // ---- causal mask + online softmax (exp2 domain) ----
            const bool diag = (k0 + 63 > q0 + wm);
            #pragma unroll
            for (int m2 = 0; m2 < 2; m2++) {
                #pragma unroll
                for (int h2 = 0; h2 < 2; h2++) {
                    const int rowg = q0 + wm + m2 * 16 + g + h2 * 8;
                    float mx = -1e30f;
                    #pragma unroll
                    for (int j = 0; j < 8; j++) {
                        float v0 = s[m2][j][h2 * 2 + 0];
                        float v1 = s[m2][j][h2 * 2 + 1];
                        if (diag) {
                            int col = k0 + j * 8 + tg * 2;
                            if (col > rowg)     v0 = -1e30f;
                            if (col + 1 > rowg) v1 = -1e30f;
                        }
                        s[m2][j][h2 * 2 + 0] = v0;
                        s[m2][j][h2 * 2 + 1] = v1;
                        mx = fmaxf(mx, fmaxf(v0, v1));
                    }
                    mx = fmaxf(mx, __shfl_xor_sync(0xffffffffu, mx, 1));
                    mx = fmaxf(mx, __shfl_xor_sync(0xffffffffu, mx, 2));

                    float mnew = fmaxf(mi[m2][h2], mx);
                    float alpha = fexp2(mi[m2][h2] - mnew);
                    float rs = 0.0f;
                    #pragma unroll
                    for (int j = 0; j < 8; j++) {
                        float p0 = fexp2(s[m2][j][h2 * 2 + 0] - mnew);
                        float p1 = fexp2(s[m2][j][h2 * 2 + 1] - mnew);
                        s[m2][j][h2 * 2 + 0] = p0;
                        s[m2][j][h2 * 2 + 1] = p1;
                        rs += p0 + p1;
                        o[m2][j][h2 * 2 + 0] *= alpha;
                        o[m2][j][h2 * 2 + 1] *= alpha;
                    }
                    rs += __shfl_xor_sync(0xffffffffu, rs, 1);
                    rs += __shfl_xor_sync(0xffffffffu, rs, 2);
                    li[m2][h2] = li[m2][h2] * alpha + rs;
                    mi[m2][h2] = mnew;
                }
            }

            // ---- O += P V (P as raw fp32 bits: HW tf32 truncation) ----
            #pragma unroll
            for (int j = 0; j < 8; j++) {
                uint32_t a[2][4];
                #pragma unroll
                for (int m2 = 0; m2 < 2; m2++) {
                    a[m2][0] = __float_as_uint(s[m2][j][0]);
                    a[m2][1] = __float_as_uint(s[m2][j][2]);
                    a[m2][2] = __float_as_uint(s[m2][j][1]);
                    a[m2][3] = __float_as_uint(s[m2][j][3]);
                }
                #pragma unroll
                for (int n = 0; n < 8; n++) {
                    uint32_t b0 = __float_as_uint(
                        Vb[(j * 8 + tg * 2) * VLD + n * 8 + g]);
                    uint32_t b1 = __float_as_uint(
                        Vb[(j * 8 + tg * 2 + 1) * VLD + n * 8 + g]);
                    #pragma unroll
                    for (int m2 = 0; m2 < 2; m2++)
                        mma_tf32(o[m2][n][0], o[m2][n][1],
                                 o[m2][n][2], o[m2][n][3],
                                 a[m2][0], a[m2][1], a[m2][2], a[m2][3],
                                 b0, b1);
                }
            }
        }
        __syncthreads();

        if (it + 2 < nk) {
            const size_t roff = base + (size_t)(it + 2) * 64 * QKV_N;
            load_k(KS_BASE + cur * K_TILE, qkv + roff + C_);
            load_v(VS_BASE + cur * V_TILE, qkv + roff + 2 * C_);
            CP_COMMIT();
        }
        if (it + 1 < nk) {
            if (it + 2 < nk) asm volatile("cp.async.wait_group 1;" ::: "memory");
            else             asm volatile("cp.async.wait_group 0;" ::: "memory");
            __syncthreads();
        }
    }

    // ---- epilogue: tf32-rounded ctx (feeds tf32 out-proj) ----
    #pragma unroll
    for (int m2 = 0; m2 < 2; m2++) {
        #pragma unroll
        for (int h2 = 0; h2 < 2; h2++) {
            const float inv = 1.0f / li[m2][h2];
            const size_t row =
                (size_t)(b * T_ + q0 + wm + m2 * 16 + g + h2 * 8);
            #pragma unroll
            for (int n = 0; n < 8; n++) {
                float2 v = make_float2(tf32f(o[m2][n][h2 * 2 + 0] * inv),
                                       tf32f(o[m2][n][h2 * 2 + 1] * inv));
                *(float2*)&ctx[row * C_ + h * D_ + n * 8 + tg * 2] = v;
            }
        }
    }
}

// ---------------------------------------------------------------------------
// Launch
// ---------------------------------------------------------------------------
extern "C" void kernel_launch(void* const* d_in, const int* in_sizes, int n_in,
                              void* d_out, int out_size)
{
    const float* x      = (const float*)d_in[0];
    const float* qkv_w  = (const float*)d_in[1];
    const float* qkv_b  = (const float*)d_in[2];
    const float* out_w  = (const float*)d_in[3];
    const float* out_b  = (const float*)d_in[4];
    float* out = (float*)d_out;

    float *qkv_ptr, *ctx_ptr, *xc_ptr, *w1_ptr, *w2_ptr;
    cudaGetSymbolAddress((void**)&qkv_ptr, g_qkv);
    cudaGetSymbolAddress((void**)&ctx_ptr, g_ctx);
    cudaGetSymbolAddress((void**)&xc_ptr, g_xc);
    cudaGetSymbolAddress((void**)&w1_ptr, g_w1);
    cudaGetSymbolAddress((void**)&w2_ptr, g_w2);

    cudaFuncSetAttribute(gemm_mma_kernel<true>,
                         cudaFuncAttributeMaxDynamicSharedMemorySize, GEMM_SMEM);
    cudaFuncSetAttribute(gemm_mma_kernel<false>,
                         cudaFuncAttributeMaxDynamicSharedMemorySize, GEMM_SMEM);
    cudaFuncSetAttribute(attn_tc_kernel,
                         cudaFuncAttributeMaxDynamicSharedMemorySize, ATT_SMEM);

    // 0) fused tf32 pre-conversion
    cvt_tf32_all<<<(N4_ALL + 255) / 256, 256>>>(
        (const float4*)x, (float4*)xc_ptr,
        (const float4*)qkv_w, (float4*)w1_ptr,
        (const float4*)out_w, (float4*)w2_ptr);

    // 1) QKV projection (q columns pre-scaled by QSCALE)
    gemm_mma_kernel<true><<<dim3(QKV_N / BN, M_ / BM), 256, GEMM_SMEM>>>(
        xc_ptr, w1_ptr, qkv_b, qkv_ptr, M_, QKV_N, C_);

    // 2) causal flash attention (exp2-domain softmax, round-10 structure)
    attn_tc_kernel<<<dim3(H_ * B_, T_ / QB), 128, ATT_SMEM>>>(qkv_ptr, ctx_ptr);

    // 3) output projection
    gemm_mma_kernel<false><<<dim3(C_ / BN, M_ / BM), 256, GEMM_SMEM>>>(
        ctx_ptr, w2_ptr, out_b, out, M_, C_, C_);
}

// round 14
// speedup vs baseline: 1.9230x; 1.7110x over previous
#include <cuda_runtime.h>
#include <cuda_fp16.h>
#include <cstdint>
#include <math.h>

// Problem constants
#define B_ 4
#define T_ 2048
#define C_ 1024
#define H_ 16
#define D_ 64
#define M_ (B_ * T_)          // 8192 rows
#define QKV_N (3 * C_)        // 3072

// softmax runs in exp2 domain: q pre-scaled by 1/sqrt(D) * log2(e)
#define QSCALE 0.18033688011112042f

// Scratch (fp16 tensors; final output f32)
__device__ __half g_qkv_h[(size_t)M_ * QKV_N];  // q pre-scaled
__device__ __half g_ctx_h[(size_t)M_ * C_];
__device__ __half g_xh[(size_t)M_ * C_];
__device__ __half g_w1h[(size_t)QKV_N * C_];
__device__ __half g_w2h[(size_t)C_ * C_];

// ===========================================================================
// helpers
// ===========================================================================
__device__ __forceinline__ uint32_t smem_u32(const void* p) {
    uint32_t a;
    asm("{ .reg .u64 t; cvta.to.shared.u64 t, %1; cvt.u32.u64 %0, t; }"
        : "=r"(a) : "l"(p));
    return a;
}

__device__ __forceinline__ void cp16(uint32_t dst, const void* src) {
    asm volatile("cp.async.cg.shared.global [%0], [%1], 16;"
        :: "r"(dst), "l"(src) : "memory");
}
#define CP_COMMIT() asm volatile("cp.async.commit_group;" ::: "memory")

__device__ __forceinline__ float fexp2(float x) {
    float y;
    asm("ex2.approx.f32 %0, %1;" : "=f"(y) : "f"(x));
    return y;
}

// pack two f32 into f16x2 (lo, hi)
__device__ __forceinline__ uint32_t f2h2(float lo, float hi) {
    uint32_t d;
    asm("cvt.rn.f16x2.f32 %0, %1, %2;" : "=r"(d) : "f"(hi), "f"(lo));
    return d;
}

__device__ __forceinline__ void mma_f16(
    float& c0, float& c1, float& c2, float& c3,
    uint32_t a0, uint32_t a1, uint32_t a2, uint32_t a3,
    uint32_t b0, uint32_t b1)
{
    asm volatile(
        "mma.sync.aligned.m16n8k16.row.col.f32.f16.f16.f32 "
        "{%0,%1,%2,%3}, {%4,%5,%6,%7}, {%8,%9}, {%0,%1,%2,%3};"
        : "+f"(c0), "+f"(c1), "+f"(c2), "+f"(c3)
        : "r"(a0), "r"(a1), "r"(a2), "r"(a3), "r"(b0), "r"(b1));
}

// ===========================================================================
// fused fp16 pre-conversion of x, qkv_w, out_w (one launch)
// ===========================================================================
#define N4_X  (M_ * C_ / 4)
#define N4_W1 (QKV_N * C_ / 4)
#define N4_W2 (C_ * C_ / 4)
#define N4_ALL (N4_X + N4_W1 + N4_W2)

__global__ void __launch_bounds__(256) cvt_h_all(
    const float4* __restrict__ x,  uint2* __restrict__ xo,
    const float4* __restrict__ w1, uint2* __restrict__ w1o,
    const float4* __restrict__ w2, uint2* __restrict__ w2o)
{
    int i = blockIdx.x * blockDim.x + threadIdx.x;
    const float4* src;
    uint2* dst;
    int k;
    if (i < N4_X)              { src = x;  dst = xo;  k = i; }
    else if (i < N4_X + N4_W1) { src = w1; dst = w1o; k = i - N4_X; }
    else if (i < N4_ALL)       { src = w2; dst = w2o; k = i - N4_X - N4_W1; }
    else return;
    float4 v = src[k];
    dst[k] = make_uint2(f2h2(v.x, v.y), f2h2(v.z, v.w));
}

// ===========================================================================
// fp16 mma.sync NT GEMM: C[m][n] = sum_k A[m][k]*W[n][k] + bias[n]
// CTA 128x128x64(fp16), 256 threads = 8 warps (2x4), warp tile 64x32.
// Rows are 128B (64 fp16) with SW128 swizzle chunk c -> c ^ (r&7):
// fragment half2 loads hit all 32 banks (chunk 2kt^g covers 8 chunks
// since g = r&7 for every fragment row). 3-stage cp.async, one sync/iter,
// 2 CTAs/SM.
// OUT_HALF: store fp16 (QKV; q cols additionally scaled by QSCALE).
// ===========================================================================
#define BM 128
#define BN 128
#define BKH 64                            // fp16 per row = 128 B
#define STGH (BM * BKH)                   // fp16 elems per matrix stage
#define NSTG 3
#define GEMM_SMEM (NSTG * 2 * STGH * 2)   // 98304 bytes

template<bool OUT_HALF>
__global__ void __launch_bounds__(256, 2) gemm_h_kernel(
    const __half* __restrict__ A, const __half* __restrict__ W,
    const float* __restrict__ bias, void* __restrict__ Cout,
    int M, int N, int K)
{
    extern __shared__ __align__(16) __half smh[];
    const uint32_t sb = smem_u32(smh);

    const int tid  = threadIdx.x;
    const int lane = tid & 31;
    const int wid  = tid >> 5;
    const int wm   = (wid & 1) * 64;
    const int wn   = (wid >> 1) * 32;
    const int g    = lane >> 2;
    const int tg   = lane & 3;

    const int m0 = blockIdx.y * BM;
    const int n0 = blockIdx.x * BN;
    const int NK = K / BKH;

    const __half* Abase = A + (size_t)m0 * K;
    const __half* Wbase = W + (size_t)n0 * K;

    // fragment fp16-offsets within a swizzled 64-fp16 row (r&7 == g for all
    // fragment rows): lo half (k..k+7): chunk 2kt^g; hi half: (2kt+1)^g
    int kofL[4], kofH[4];
    #pragma unroll
    for (int kt = 0; kt < 4; kt++) {
        kofL[kt] = (((2 * kt) ^ g) << 3) + 2 * tg;
        kofH[kt] = (((2 * kt + 1) ^ g) << 3) + 2 * tg;
    }

    auto load_stage = [&](int kc) {
        const int st = kc % NSTG;
        const uint32_t sA = sb + (uint32_t)st * 2 * STGH * 2;
        const uint32_t sB = sA + STGH * 2;
        const int kOff = kc * BKH;
        #pragma unroll
        for (int t = 0; t < 4; t++) {
            int idx = tid + t * 256;       // 0..1023
            int r = idx >> 3;              // row 0..127
            int c = idx & 7;               // 16B chunk
            uint32_t off = (uint32_t)(r * 128 + ((c ^ (r & 7)) << 4));
            cp16(sA + off, Abase + (size_t)r * K + kOff + c * 8);
            cp16(sB + off, Wbase + (size_t)r * K + kOff + c * 8);
        }
        CP_COMMIT();
    };

    float acc[4][4][4] = {};

    load_stage(0);
    if (NK > 1) load_stage(1);

    for (int kc = 0; kc < NK; kc++) {
        if (kc + 1 < NK) asm volatile("cp.async.wait_group 1;" ::: "memory");
        else             asm volatile("cp.async.wait_group 0;" ::: "memory");
        __syncthreads();

        const int st = kc % NSTG;
        const __half* As = smh + st * 2 * STGH;
        const __half* Bs = As + STGH;

        #pragma unroll
        for (int kt = 0; kt < 4; kt++) {
            uint32_t af[4][4], bf[4][2];
            #pragma unroll
            for (int i = 0; i < 4; i++) {
                const __half* ap = As + (wm + i * 16 + g) * 64;
                af[i][0] = *(const uint32_t*)(ap + kofL[kt]);
                af[i][1] = *(const uint32_t*)(ap + 8 * 64 + kofL[kt]);
                af[i][2] = *(const uint32_t*)(ap + kofH[kt]);
                af[i][3] = *(const uint32_t*)(ap + 8 * 64 + kofH[kt]);
            }
            #pragma unroll
            for (int j = 0; j < 4; j++) {
                const __half* bp = Bs + (wn + j * 8 + g) * 64;
                bf[j][0] = *(const uint32_t*)(bp + kofL[kt]);
                bf[j][1] = *(const uint32_t*)(bp + kofH[kt]);
            }
            #pragma unroll
            for (int i = 0; i < 4; i++)
                #pragma unroll
                for (int j = 0; j < 4; j++)
                    mma_f16(acc[i][j][0], acc[i][j][1],
                            acc[i][j][2], acc[i][j][3],
                            af[i][0], af[i][1], af[i][2], af[i][3],
                            bf[j][0], bf[j][1]);
        }

        if (kc + 2 < NK) load_stage(kc + 2);
    }

    // q columns (n0 < C_) of the QKV output get the softmax scale folded in
    const float qs = (OUT_HALF && n0 < C_) ? QSCALE : 1.0f;

    #pragma unroll
    for (int i = 0; i < 4; i++) {
        const int row = m0 + wm + i * 16 + g;
        #pragma unroll
        for (int j = 0; j < 4; j++) {
            const int col = n0 + wn + j * 8 + tg * 2;
            float b0 = __ldg(bias + col);
            float b1 = __ldg(bias + col + 1);
            if (OUT_HALF) {
                __half* Ch = (__half*)Cout;
                *(uint32_t*)&Ch[(size_t)row * N + col] =
                    f2h2((acc[i][j][0] + b0) * qs, (acc[i][j][1] + b1) * qs);
                *(uint32_t*)&Ch[(size_t)(row + 8) * N + col] =
                    f2h2((acc[i][j][2] + b0) * qs, (acc[i][j][3] + b1) * qs);
            } else {
                float* Cf = (float*)Cout;
                *(float2*)&Cf[(size_t)row * N + col] =
                    make_float2(acc[i][j][0] + b0, acc[i][j][1] + b1);
                *(float2*)&Cf[(size_t)(row + 8) * N + col] =
                    make_float2(acc[i][j][2] + b0, acc[i][j][3] + b1);
            }
        }
    }
}

// ===========================================================================
// fp16 tensor-core flash attention (causal, exp2-domain softmax).
// Round-13 structure (QB=128, 128 thr = 4 warps x 32 q-rows, 2 CTAs/SM,
// double-buffered K/V, constant loop bounds), fp16 data:
//  - Q/K/V in smem as fp16, LD=72 fp16 (144B rows; stride 36 words == 4
//    mod 32 -> conflict-free half2 fragment loads, 16-bank clean V u16)
//  - QK and PV via m16n8k16 fp16 (half the MMAs + half the smem bytes)
//  - P packs natively: a0/a1 = s[2kt] c0..c3, a2/a3 = s[2kt+1] c0..c3
// ===========================================================================
#define QB 128
#define ALDH 72                                  // fp16 stride
#define KV_TILEH (64 * ALDH)                     // fp16 per tile
#define Q_HALFS (QB * ALDH)
#define KS_BASE Q_HALFS
#define VS_BASE (Q_HALFS + 2 * KV_TILEH)
#define ATT_SMEM ((VS_BASE + 2 * KV_TILEH) * 2)  // 55296 B

__global__ void __launch_bounds__(128, 2) attn_h_kernel(
    const __half* __restrict__ qkv, __half* __restrict__ ctx)
{
    extern __shared__ __align__(16) __half smh[];
    const __half* Qs = smh;
    const uint32_t sb = smem_u32(smh);

    const int tid  = threadIdx.x;
    const int lane = tid & 31;
    const int wid  = tid >> 5;
    const int g    = lane >> 2;
    const int tg   = lane & 3;
    const int wm   = wid * 32;

    const int bh = blockIdx.x;
    const int b  = bh >> 4;
    const int h  = bh & 15;
    const int qblock = 15 - (int)blockIdx.y;
    const int q0 = qblock << 7;
    const int nk = (qblock + 1) * 2;

    const size_t base = (size_t)b * T_ * QKV_N + (size_t)h * D_;

    // K/V tile: 64 rows x 8 chunks(16B) = 512 chunks, 128 thr -> 4 each
    auto load_kv = [&](int fbase, const __half* gsrc) {
        #pragma unroll
        for (int t = 0; t < 4; t++) {
            int idx = tid + t * 128;
            int r = idx >> 3;
            int c = idx & 7;
            cp16(sb + (uint32_t)(fbase + r * ALDH) * 2 + c * 16,
                 gsrc + (size_t)r * QKV_N + c * 8);
        }
    };

    {
        const __half* qsrc = qkv + base + (size_t)q0 * QKV_N;
        #pragma unroll
        for (int t = 0; t < 8; t++) {
            int idx = tid + t * 128;
            int r = idx >> 3;
            int c = idx & 7;
            cp16(sb + (uint32_t)(r * ALDH) * 2 + c * 16,
                 qsrc + (size_t)r * QKV_N + c * 8);
        }
        load_kv(KS_BASE, qkv + base + C_);
        load_kv(VS_BASE, qkv + base + 2 * C_);
        CP_COMMIT();
        load_kv(KS_BASE + KV_TILEH, qkv + base + (size_t)64 * QKV_N + C_);
        load_kv(VS_BASE + KV_TILEH, qkv + base + (size_t)64 * QKV_N + 2 * C_);
        CP_COMMIT();
    }
    asm volatile("cp.async.wait_group 1;" ::: "memory");
    __syncthreads();

    float o[2][8][4] = {};
    float mi[2][2] = {{-1e30f, -1e30f}, {-1e30f, -1e30f}};
    float li[2][2] = {};

    for (int it = 0; it < nk; it++) {
        const int cur = it & 1;
        const int k0 = it * 64;
        const __half* Kb = smh + KS_BASE + cur * KV_TILEH;
        const uint16_t* Vb =
            (const uint16_t*)(smh + VS_BASE + cur * KV_TILEH);

        if (k0 <= q0 + wm + 31) {
            // ---- S = Q K^T (fp16 m16n8k16; q pre-scaled, exp2 domain) ----
            float s[2][8][4] = {};
            #pragma unroll
            for (int kt = 0; kt < 4; kt++) {
                const int kk = kt * 16 + 2 * tg;
                uint32_t af[2][4];
                #pragma unroll
                for (int m2 = 0; m2 < 2; m2++) {
                    const __half* qp = Qs + (wm + m2 * 16 + g) * ALDH + kk;
                    af[m2][0] = *(const uint32_t*)qp;
                    af[m2][1] = *(const uint32_t*)(qp + 8 * ALDH);
                    af[m2][2] = *(const uint32_t*)(qp + 8);
                    af[m2][3] = *(const uint32_t*)(qp + 8 * ALDH + 8);
                }
                #pragma unroll
                for (int j = 0; j < 8; j++) {
                    const __half* kp = Kb + (j * 8 + g) * ALDH + kk;
                    uint32_t b0 = *(const uint32_t*)kp;
                    uint32_t b1 = *(const uint32_t*)(kp + 8);
                    #pragma unroll
                    for (int m2 = 0; m2 < 2; m2++)
                        mma_f16(s[m2][j][0], s[m2][j][1],
                                s[m2][j][2], s[m2][j][3],
                                af[m2][0], af[m2][1], af[m2][2], af[m2][3],
                                b0, b1);
                }
            }

            // ---- causal mask + online softmax (exp2 domain) ----
            const bool diag = (k0 + 63 > q0 + wm);
            #pragma unroll
            for (int m2 = 0; m2 < 2; m2++) {
                #pragma unroll
                for (int h2 = 0; h2 < 2; h2++) {
                    const int rowg = q0 + wm + m2 * 16 + g + h2 * 8;
                    float mx = -1e30f;
                    #pragma unroll
                    for (int j = 0; j < 8; j++) {
                        float v0 = s[m2][j][h2 * 2 + 0];
                        float v1 = s[m2][j][h2 * 2 + 1];
                        if (diag) {
                            int col = k0 + j * 8 + tg * 2;
                            if (col > rowg)     v0 = -1e30f;
                            if (col + 1 > rowg) v1 = -1e30f;
                        }
                        s[m2][j][h2 * 2 + 0] = v0;
                        s[m2][j][h2 * 2 + 1] = v1;
                        mx = fmaxf(mx, fmaxf(v0, v1));
                    }
                    mx = fmaxf(mx, __shfl_xor_sync(0xffffffffu, mx, 1));
                    mx = fmaxf(mx, __shfl_xor_sync(0xffffffffu, mx, 2));

                    float mnew = fmaxf(mi[m2][h2], mx);
                    float alpha = fexp2(mi[m2][h2] - mnew);
                    float rs = 0.0f;
                    #pragma unroll
                    for (int j = 0; j < 8; j++) {
                        float p0 = fexp2(s[m2][j][h2 * 2 + 0] - mnew);
                        float p1 = fexp2(s[m2][j][h2 * 2 + 1] - mnew);
                        s[m2][j][h2 * 2 + 0] = p0;
                        s[m2][j][h2 * 2 + 1] = p1;
                        rs += p0 + p1;
                        o[m2][j][h2 * 2 + 0] *= alpha;
                        o[m2][j][h2 * 2 + 1] *= alpha;
                    }
                    rs += __shfl_xor_sync(0xffffffffu, rs, 1);
                    rs += __shfl_xor_sync(0xffffffffu, rs, 2);
                    li[m2][h2] = li[m2][h2] * alpha + rs;
                    mi[m2][h2] = mnew;
                }
            }

            // ---- O += P V (fp16 m16n8k16; P packed from s registers) ----
            #pragma unroll
            for (int kt = 0; kt < 4; kt++) {
                uint32_t a[2][4];
                #pragma unroll
                for (int m2 = 0; m2 < 2; m2++) {
                    a[m2][0] = f2h2(s[m2][2 * kt][0],     s[m2][2 * kt][1]);
                    a[m2][1] = f2h2(s[m2][2 * kt][2],     s[m2][2 * kt][3]);
                    a[m2][2] = f2h2(s[m2][2 * kt + 1][0], s[m2][2 * kt + 1][1]);
                    a[m2][3] = f2h2(s[m2][2 * kt + 1][2], s[m2][2 * kt + 1][3]);
                }
                const int kv0 = kt * 16 + 2 * tg;
                #pragma unroll
                for (int n = 0; n < 8; n++) {
                    const int colv = n * 8 + g;
                    uint32_t b0 = (uint32_t)Vb[kv0 * ALDH + colv]
                        | ((uint32_t)Vb[(kv0 + 1) * ALDH + colv] << 16);
                    uint32_t b1 = (uint32_t)Vb[(kv0 + 8) * ALDH + colv]
                        | ((uint32_t)Vb[(kv0 + 9) * ALDH + colv] << 16);
                    #pragma unroll
                    for (int m2 = 0; m2 < 2; m2++)
                        mma_f16(o[m2][n][0], o[m2][n][1],
                                o[m2][n][2], o[m2][n][3],
                                a[m2][0], a[m2][1], a[m2][2], a[m2][3],
                                b0, b1);
                }
            }
        }
        __syncthreads();

        if (it + 2 < nk) {
            const size_t roff = base + (size_t)(it + 2) * 64 * QKV_N;
            load_kv(KS_BASE + cur * KV_TILEH, qkv + roff + C_);
            load_kv(VS_BASE + cur * KV_TILEH, qkv + roff + 2 * C_);
            CP_COMMIT();
        }
        if (it + 1 < nk) {
            if (it + 2 < nk) asm volatile("cp.async.wait_group 1;" ::: "memory");
            else             asm volatile("cp.async.wait_group 0;" ::: "memory");
            __syncthreads();
        }
    }

    // ---- epilogue: fp16 ctx (feeds fp16 out-proj) ----
    #pragma unroll
    for (int m2 = 0; m2 < 2; m2++) {
        #pragma unroll
        for (int h2 = 0; h2 < 2; h2++) {
            const float inv = 1.0f / li[m2][h2];
            const size_t row =
                (size_t)(b * T_ + q0 + wm + m2 * 16 + g + h2 * 8);
            #pragma unroll
            for (int n = 0; n < 8; n++) {
                *(uint32_t*)&ctx[row * C_ + h * D_ + n * 8 + tg * 2] =
                    f2h2(o[m2][n][h2 * 2 + 0] * inv,
                         o[m2][n][h2 * 2 + 1] * inv);
            }
        }
    }
}

// ---------------------------------------------------------------------------
// Launch
// ---------------------------------------------------------------------------
extern "C" void kernel_launch(void* const* d_in, const int* in_sizes, int n_in,
                              void* d_out, int out_size)
{
    const float* x      = (const float*)d_in[0];
    const float* qkv_w  = (const float*)d_in[1];
    const float* qkv_b  = (const float*)d_in[2];
    const float* out_w  = (const float*)d_in[3];
    const float* out_b  = (const float*)d_in[4];
    float* out = (float*)d_out;

    __half *qkv_ptr, *ctx_ptr, *xh_ptr, *w1h_ptr, *w2h_ptr;
    cudaGetSymbolAddress((void**)&qkv_ptr, g_qkv_h);
    cudaGetSymbolAddress((void**)&ctx_ptr, g_ctx_h);
    cudaGetSymbolAddress((void**)&xh_ptr, g_xh);
    cudaGetSymbolAddress((void**)&w1h_ptr, g_w1h);
    cudaGetSymbolAddress((void**)&w2h_ptr, g_w2h);

    cudaFuncSetAttribute(gemm_h_kernel<true>,
                         cudaFuncAttributeMaxDynamicSharedMemorySize, GEMM_SMEM);
    cudaFuncSetAttribute(gemm_h_kernel<false>,
                         cudaFuncAttributeMaxDynamicSharedMemorySize, GEMM_SMEM);
    cudaFuncSetAttribute(attn_h_kernel,
                         cudaFuncAttributeMaxDynamicSharedMemorySize, ATT_SMEM);

    // 0) fused fp16 pre-conversion
    cvt_h_all<<<(N4_ALL + 255) / 256, 256>>>(
        (const float4*)x, (uint2*)xh_ptr,
        (const float4*)qkv_w, (uint2*)w1h_ptr,
        (const float4*)out_w, (uint2*)w2h_ptr);

    // 1) QKV projection (fp16 out, q columns pre-scaled by QSCALE)
    gemm_h_kernel<true><<<dim3(QKV_N / BN, M_ / BM), 256, GEMM_SMEM>>>(
        xh_ptr, w1h_ptr, qkv_b, qkv_ptr, M_, QKV_N, C_);

    // 2) causal flash attention (fp16, exp2-domain softmax)
    attn_h_kernel<<<dim3(H_ * B_, T_ / QB), 128, ATT_SMEM>>>(qkv_ptr, ctx_ptr);

    // 3) output projection (fp16 in, f32 out)
    gemm_h_kernel<false><<<dim3(C_ / BN, M_ / BM), 256, GEMM_SMEM>>>(
        ctx_ptr, w2h_ptr, out_b, out, M_, C_, C_);
}

// round 15
// speedup vs baseline: 2.1852x; 1.1363x over previous
#include <cuda_runtime.h>
#include <cuda_fp16.h>
#include <cstdint>
#include <math.h>

// Problem constants
#define B_ 4
#define T_ 2048
#define C_ 1024
#define H_ 16
#define D_ 64
#define M_ (B_ * T_)          // 8192 rows
#define QKV_N (3 * C_)        // 3072

// softmax runs in exp2 domain: q pre-scaled by 1/sqrt(D) * log2(e)
#define QSCALE 0.18033688011112042f

// Scratch (fp16 tensors; final output f32)
__device__ __half g_qkv_h[(size_t)M_ * QKV_N];  // q pre-scaled
__device__ __half g_ctx_h[(size_t)M_ * C_];
__device__ __half g_xh[(size_t)M_ * C_];
__device__ __half g_w1h[(size_t)QKV_N * C_];
__device__ __half g_w2h[(size_t)C_ * C_];

// ===========================================================================
// helpers
// ===========================================================================
__device__ __forceinline__ uint32_t smem_u32(const void* p) {
    uint32_t a;
    asm("{ .reg .u64 t; cvta.to.shared.u64 t, %1; cvt.u32.u64 %0, t; }"
        : "=r"(a) : "l"(p));
    return a;
}

__device__ __forceinline__ void cp16(uint32_t dst, const void* src) {
    asm volatile("cp.async.cg.shared.global [%0], [%1], 16;"
        :: "r"(dst), "l"(src) : "memory");
}
#define CP_COMMIT() asm volatile("cp.async.commit_group;" ::: "memory")

__device__ __forceinline__ float fexp2(float x) {
    float y;
    asm("ex2.approx.f32 %0, %1;" : "=f"(y) : "f"(x));
    return y;
}

// pack two f32 into f16x2 (lo, hi)
__device__ __forceinline__ uint32_t f2h2(float lo, float hi) {
    uint32_t d;
    asm("cvt.rn.f16x2.f32 %0, %1, %2;" : "=r"(d) : "f"(hi), "f"(lo));
    return d;
}

__device__ __forceinline__ void ldsm_x4(
    uint32_t& r0, uint32_t& r1, uint32_t& r2, uint32_t& r3, uint32_t addr)
{
    asm volatile(
        "ldmatrix.sync.aligned.m8n8.x4.shared.b16 {%0,%1,%2,%3}, [%4];"
        : "=r"(r0), "=r"(r1), "=r"(r2), "=r"(r3) : "r"(addr));
}

__device__ __forceinline__ void ldsm_x4_t(
    uint32_t& r0, uint32_t& r1, uint32_t& r2, uint32_t& r3, uint32_t addr)
{
    asm volatile(
        "ldmatrix.sync.aligned.m8n8.x4.trans.shared.b16 {%0,%1,%2,%3}, [%4];"
        : "=r"(r0), "=r"(r1), "=r"(r2), "=r"(r3) : "r"(addr));
}

__device__ __forceinline__ void mma_f16(
    float& c0, float& c1, float& c2, float& c3,
    uint32_t a0, uint32_t a1, uint32_t a2, uint32_t a3,
    uint32_t b0, uint32_t b1)
{
    asm volatile(
        "mma.sync.aligned.m16n8k16.row.col.f32.f16.f16.f32 "
        "{%0,%1,%2,%3}, {%4,%5,%6,%7}, {%8,%9}, {%0,%1,%2,%3};"
        : "+f"(c0), "+f"(c1), "+f"(c2), "+f"(c3)
        : "r"(a0), "r"(a1), "r"(a2), "r"(a3), "r"(b0), "r"(b1));
}

// ===========================================================================
// fused fp16 pre-conversion of x, qkv_w, out_w (one launch)
// ===========================================================================
#define N4_X  (M_ * C_ / 4)
#define N4_W1 (QKV_N * C_ / 4)
#define N4_W2 (C_ * C_ / 4)
#define N4_ALL (N4_X + N4_W1 + N4_W2)

__global__ void __launch_bounds__(256) cvt_h_all(
    const float4* __restrict__ x,  uint2* __restrict__ xo,
    const float4* __restrict__ w1, uint2* __restrict__ w1o,
    const float4* __restrict__ w2, uint2* __restrict__ w2o)
{
    int i = blockIdx.x * blockDim.x + threadIdx.x;
    const float4* src;
    uint2* dst;
    int k;
    if (i < N4_X)              { src = x;  dst = xo;  k = i; }
    else if (i < N4_X + N4_W1) { src = w1; dst = w1o; k = i - N4_X; }
    else if (i < N4_ALL)       { src = w2; dst = w2o; k = i - N4_X - N4_W1; }
    else return;
    float4 v = src[k];
    dst[k] = make_uint2(f2h2(v.x, v.y), f2h2(v.z, v.w));
}

// ===========================================================================
// fp16 mma.sync NT GEMM with ldmatrix fragment loads.
// CTA 128x128x64(fp16), 256 threads = 8 warps (2x4), warp tile 64x32.
// 128B rows, swizzle chunk c -> c ^ (r&7); 3-stage cp.async, one sync/iter,
// 2 CTAs/SM.
// ===========================================================================
#define BM 128
#define BN 128
#define BKH 64                            // fp16 per row = 128 B
#define STGH (BM * BKH)                   // fp16 elems per matrix stage
#define NSTG 3
#define GEMM_SMEM (NSTG * 2 * STGH * 2)   // 98304 bytes

template<bool OUT_HALF>
__global__ void __launch_bounds__(256, 2) gemm_h_kernel(
    const __half* __restrict__ A, const __half* __restrict__ W,
    const float* __restrict__ bias, void* __restrict__ Cout,
    int M, int N, int K)
{
    extern __shared__ __align__(16) __half smh[];
    const uint32_t sb = smem_u32(smh);

    const int tid  = threadIdx.x;
    const int lane = tid & 31;
    const int wid  = tid >> 5;
    const int wm   = (wid & 1) * 64;
    const int wn   = (wid >> 1) * 32;
    const int g    = lane >> 2;
    const int tg   = lane & 3;

    const int m0 = blockIdx.y * BM;
    const int n0 = blockIdx.x * BN;
    const int NK = K / BKH;

    const __half* Abase = A + (size_t)m0 * K;
    const __half* Wbase = W + (size_t)n0 * K;

    // ldmatrix lane decomposition
    const int sel = lane >> 3;            // matrix index 0..3
    const int rr  = lane & 7;             // row within matrix
    // A mats: (m-lo,k-lo),(m-hi,k-lo),(m-lo,k-hi),(m-hi,k-hi)
    const int aRow0 = wm + ((sel & 1) << 3) + rr;
    const int aKb   = sel >> 1;
    // B mats: (j0,k-lo),(j0,k-hi),(j1,k-lo),(j1,k-hi)
    const int bRow0 = wn + ((sel >> 1) << 3) + rr;
    const int bKb   = sel & 1;

    auto load_stage = [&](int kc) {
        const int st = kc % NSTG;
        const uint32_t sA = sb + (uint32_t)st * 2 * STGH * 2;
        const uint32_t sB = sA + STGH * 2;
        const int kOff = kc * BKH;
        #pragma unroll
        for (int t = 0; t < 4; t++) {
            int idx = tid + t * 256;
            int r = idx >> 3;
            int c = idx & 7;
            uint32_t off = (uint32_t)(r * 128 + ((c ^ (r & 7)) << 4));
            cp16(sA + off, Abase + (size_t)r * K + kOff + c * 8);
            cp16(sB + off, Wbase + (size_t)r * K + kOff + c * 8);
        }
        CP_COMMIT();
    };

    float acc[4][4][4] = {};

    load_stage(0);
    if (NK > 1) load_stage(1);

    for (int kc = 0; kc < NK; kc++) {
        if (kc + 1 < NK) asm volatile("cp.async.wait_group 1;" ::: "memory");
        else             asm volatile("cp.async.wait_group 0;" ::: "memory");
        __syncthreads();

        const int st = kc % NSTG;
        const uint32_t sA = sb + (uint32_t)st * 2 * STGH * 2;
        const uint32_t sB = sA + STGH * 2;

        #pragma unroll
        for (int kt = 0; kt < 4; kt++) {
            uint32_t af[4][4], bf[4][2];
            #pragma unroll
            for (int i = 0; i < 4; i++) {
                int row = aRow0 + i * 16;
                int ch  = kt * 2 + aKb;
                ldsm_x4(af[i][0], af[i][1], af[i][2], af[i][3],
                        sA + (uint32_t)(row * 128 + ((ch ^ (row & 7)) << 4)));
            }
            #pragma unroll
            for (int jp = 0; jp < 2; jp++) {
                int row = bRow0 + jp * 16;
                int ch  = kt * 2 + bKb;
                ldsm_x4(bf[jp * 2][0], bf[jp * 2][1],
                        bf[jp * 2 + 1][0], bf[jp * 2 + 1][1],
                        sB + (uint32_t)(row * 128 + ((ch ^ (row & 7)) << 4)));
            }
            #pragma unroll
            for (int i = 0; i < 4; i++)
                #pragma unroll
                for (int j = 0; j < 4; j++)
                    mma_f16(acc[i][j][0], acc[i][j][1],
                            acc[i][j][2], acc[i][j][3],
                            af[i][0], af[i][1], af[i][2], af[i][3],
                            bf[j][0], bf[j][1]);
        }

        if (kc + 2 < NK) load_stage(kc + 2);
    }

    // q columns (n0 < C_) of the QKV output get the softmax scale folded in
    const float qs = (OUT_HALF && n0 < C_) ? QSCALE : 1.0f;

    #pragma unroll
    for (int i = 0; i < 4; i++) {
        const int row = m0 + wm + i * 16 + g;
        #pragma unroll
        for (int j = 0; j < 4; j++) {
            const int col = n0 + wn + j * 8 + tg * 2;
            float b0 = __ldg(bias + col);
            float b1 = __ldg(bias + col + 1);
            if (OUT_HALF) {
                __half* Ch = (__half*)Cout;
                *(uint32_t*)&Ch[(size_t)row * N + col] =
                    f2h2((acc[i][j][0] + b0) * qs, (acc[i][j][1] + b1) * qs);
                *(uint32_t*)&Ch[(size_t)(row + 8) * N + col] =
                    f2h2((acc[i][j][2] + b0) * qs, (acc[i][j][3] + b1) * qs);
            } else {
                float* Cf = (float*)Cout;
                *(float2*)&Cf[(size_t)row * N + col] =
                    make_float2(acc[i][j][0] + b0, acc[i][j][1] + b1);
                *(float2*)&Cf[(size_t)(row + 8) * N + col] =
                    make_float2(acc[i][j][2] + b0, acc[i][j][3] + b1);
            }
        }
    }
}

// ===========================================================================
// fp16 tensor-core flash attention with ldmatrix fragment loads.
// QB=128, 128 thr = 4 warps x 32 q-rows, 2 CTAs/SM, double-buffered K/V.
// Q/K fragments: ldmatrix non-trans; V: ldmatrix trans from [k][n] rows.
// Stride 72 fp16 (144 B = 9 x 16B) makes all LDSM accesses conflict-free.
// ===========================================================================
#define QB 128
#define ALDH 72                                  // fp16 stride
#define KV_TILEH (64 * ALDH)                     // fp16 per tile
#define Q_HALFS (QB * ALDH)
#define KS_BASE Q_HALFS
#define VS_BASE (Q_HALFS + 2 * KV_TILEH)
#define ATT_SMEM ((VS_BASE + 2 * KV_TILEH) * 2)  // 55296 B

__global__ void __launch_bounds__(128, 2) attn_h_kernel(
    const __half* __restrict__ qkv, __half* __restrict__ ctx)
{
    extern __shared__ __align__(16) __half smh[];
    const uint32_t sb = smem_u32(smh);

    const int tid  = threadIdx.x;
    const int lane = tid & 31;
    const int wid  = tid >> 5;
    const int g    = lane >> 2;
    const int tg   = lane & 3;
    const int wm   = wid * 32;

    const int bh = blockIdx.x;
    const int b  = bh >> 4;
    const int h  = bh & 15;
    const int qblock = 15 - (int)blockIdx.y;
    const int q0 = qblock << 7;
    const int nk = (qblock + 1) * 2;

    const size_t base = (size_t)b * T_ * QKV_N + (size_t)h * D_;

    // ldmatrix lane decomposition
    const int sel = lane >> 3;
    const int rr  = lane & 7;
    // Q (A-op): mats (m-lo,k-lo),(m-hi,k-lo),(m-lo,k-hi),(m-hi,k-hi)
    const int qRow0 = wm + ((sel & 1) << 3) + rr;
    const int qKb   = sel >> 1;
    // K (B-op): mats (j0,k-lo),(j0,k-hi),(j1,k-lo),(j1,k-hi)
    const int kRow0 = ((sel >> 1) << 3) + rr;
    const int kKb   = sel & 1;
    // V (B-op, trans): mats (k-lo,n0),(k-hi,n0),(k-lo,n1),(k-hi,n1)
    const int vRow0 = ((sel & 1) << 3) + rr;
    const int vCol0 = (sel >> 1) << 3;

    auto load_kv = [&](int fbase, const __half* gsrc) {
        #pragma unroll
        for (int t = 0; t < 4; t++) {
            int idx = tid + t * 128;
            int r = idx >> 3;
            int c = idx & 7;
            cp16(sb + (uint32_t)(fbase + r * ALDH) * 2 + c * 16,
                 gsrc + (size_t)r * QKV_N + c * 8);
        }
    };

    {
        const __half* qsrc = qkv + base + (size_t)q0 * QKV_N;
        #pragma unroll
        for (int t = 0; t < 8; t++) {
            int idx = tid + t * 128;
            int r = idx >> 3;
            int c = idx & 7;
            cp16(sb + (uint32_t)(r * ALDH) * 2 + c * 16,
                 qsrc + (size_t)r * QKV_N + c * 8);
        }
        load_kv(KS_BASE, qkv + base + C_);
        load_kv(VS_BASE, qkv + base + 2 * C_);
        CP_COMMIT();
        load_kv(KS_BASE + KV_TILEH, qkv + base + (size_t)64 * QKV_N + C_);
        load_kv(VS_BASE + KV_TILEH, qkv + base + (size_t)64 * QKV_N + 2 * C_);
        CP_COMMIT();
    }
    asm volatile("cp.async.wait_group 1;" ::: "memory");
    __syncthreads();

    float o[2][8][4] = {};
    float mi[2][2] = {{-1e30f, -1e30f}, {-1e30f, -1e30f}};
    float li[2][2] = {};

    for (int it = 0; it < nk; it++) {
        const int cur = it & 1;
        const int k0 = it * 64;
        const uint32_t sbK = sb + (uint32_t)(KS_BASE + cur * KV_TILEH) * 2;
        const uint32_t sbV = sb + (uint32_t)(VS_BASE + cur * KV_TILEH) * 2;

        if (k0 <= q0 + wm + 31) {
            // ---- S = Q K^T (fp16 m16n8k16; q pre-scaled, exp2 domain) ----
            float s[2][8][4] = {};
            #pragma unroll
            for (int kt = 0; kt < 4; kt++) {
                uint32_t af[2][4];
                #pragma unroll
                for (int m2 = 0; m2 < 2; m2++) {
                    int row = qRow0 + m2 * 16;
                    int ch  = kt * 2 + qKb;
                    ldsm_x4(af[m2][0], af[m2][1], af[m2][2], af[m2][3],
                            sb + (uint32_t)(row * ALDH + ch * 8) * 2);
                }
                uint32_t bK[8][2];
                #pragma unroll
                for (int jp = 0; jp < 4; jp++) {
                    int row = kRow0 + jp * 16;
                    int ch  = kt * 2 + kKb;
                    ldsm_x4(bK[jp * 2][0], bK[jp * 2][1],
                            bK[jp * 2 + 1][0], bK[jp * 2 + 1][1],
                            sbK + (uint32_t)(row * ALDH + ch * 8) * 2);
                }
                #pragma unroll
                for (int j = 0; j < 8; j++)
                    #pragma unroll
                    for (int m2 = 0; m2 < 2; m2++)
                        mma_f16(s[m2][j][0], s[m2][j][1],
                                s[m2][j][2], s[m2][j][3],
                                af[m2][0], af[m2][1], af[m2][2], af[m2][3],
                                bK[j][0], bK[j][1]);
            }

            // ---- causal mask + online softmax (exp2 domain) ----
            const bool diag = (k0 + 63 > q0 + wm);
            #pragma unroll
            for (int m2 = 0; m2 < 2; m2++) {
                #pragma unroll
                for (int h2 = 0; h2 < 2; h2++) {
                    const int rowg = q0 + wm + m2 * 16 + g + h2 * 8;
                    float mx = -1e30f;
                    #pragma unroll
                    for (int j = 0; j < 8; j++) {
                        float v0 = s[m2][j][h2 * 2 + 0];
                        float v1 = s[m2][j][h2 * 2 + 1];
                        if (diag) {
                            int col = k0 + j * 8 + tg * 2;
                            if (col > rowg)     v0 = -1e30f;
                            if (col + 1 > rowg) v1 = -1e30f;
                        }
                        s[m2][j][h2 * 2 + 0] = v0;
                        s[m2][j][h2 * 2 + 1] = v1;
                        mx = fmaxf(mx, fmaxf(v0, v1));
                    }
                    mx = fmaxf(mx, __shfl_xor_sync(0xffffffffu, mx, 1));
                    mx = fmaxf(mx, __shfl_xor_sync(0xffffffffu, mx, 2));

                    float mnew = fmaxf(mi[m2][h2], mx);
                    float alpha = fexp2(mi[m2][h2] - mnew);
                    float rs = 0.0f;
                    #pragma unroll
                    for (int j = 0; j < 8; j++) {
                        float p0 = fexp2(s[m2][j][h2 * 2 + 0] - mnew);
                        float p1 = fexp2(s[m2][j][h2 * 2 + 1] - mnew);
                        s[m2][j][h2 * 2 + 0] = p0;
                        s[m2][j][h2 * 2 + 1] = p1;
                        rs += p0 + p1;
                        o[m2][j][h2 * 2 + 0] *= alpha;
                        o[m2][j][h2 * 2 + 1] *= alpha;
                    }
                    rs += __shfl_xor_sync(0xffffffffu, rs, 1);
                    rs += __shfl_xor_sync(0xffffffffu, rs, 2);
                    li[m2][h2] = li[m2][h2] * alpha + rs;
                    mi[m2][h2] = mnew;
                }
            }

            // ---- O += P V (fp16; P packed from s, V via ldmatrix.trans) ----
            #pragma unroll
            for (int kt = 0; kt < 4; kt++) {
                uint32_t a[2][4];
                #pragma unroll
                for (int m2 = 0; m2 < 2; m2++) {
                    a[m2][0] = f2h2(s[m2][2 * kt][0],     s[m2][2 * kt][1]);
                    a[m2][1] = f2h2(s[m2][2 * kt][2],     s[m2][2 * kt][3]);
                    a[m2][2] = f2h2(s[m2][2 * kt + 1][0], s[m2][2 * kt + 1][1]);
                    a[m2][3] = f2h2(s[m2][2 * kt + 1][2], s[m2][2 * kt + 1][3]);
                }
                uint32_t bV[8][2];
                #pragma unroll
                for (int np = 0; np < 4; np++) {
                    int row = vRow0 + kt * 16;
                    int col = vCol0 + np * 16;
                    ldsm_x4_t(bV[np * 2][0], bV[np * 2][1],
                              bV[np * 2 + 1][0], bV[np * 2 + 1][1],
                              sbV + (uint32_t)(row * ALDH + col) * 2);
                }
                #pragma unroll
                for (int n = 0; n < 8; n++)
                    #pragma unroll
                    for (int m2 = 0; m2 < 2; m2++)
                        mma_f16(o[m2][n][0], o[m2][n][1],
                                o[m2][n][2], o[m2][n][3],
                                a[m2][0], a[m2][1], a[m2][2], a[m2][3],
                                bV[n][0], bV[n][1]);
            }
        }
        __syncthreads();

        if (it + 2 < nk) {
            const size_t roff = base + (size_t)(it + 2) * 64 * QKV_N;
            load_kv(KS_BASE + cur * KV_TILEH, qkv + roff + C_);
            load_kv(VS_BASE + cur * KV_TILEH, qkv + roff + 2 * C_);
            CP_COMMIT();
        }
        if (it + 1 < nk) {
            if (it + 2 < nk) asm volatile("cp.async.wait_group 1;" ::: "memory");
            else             asm volatile("cp.async.wait_group 0;" ::: "memory");
            __syncthreads();
        }
    }

    // ---- epilogue: fp16 ctx (feeds fp16 out-proj) ----
    #pragma unroll
    for (int m2 = 0; m2 < 2; m2++) {
        #pragma unroll
        for (int h2 = 0; h2 < 2; h2++) {
            const float inv = 1.0f / li[m2][h2];
            const size_t row =
                (size_t)(b * T_ + q0 + wm + m2 * 16 + g + h2 * 8);
            #pragma unroll
            for (int n = 0; n < 8; n++) {
                *(uint32_t*)&ctx[row * C_ + h * D_ + n * 8 + tg * 2] =
                    f2h2(o[m2][n][h2 * 2 + 0] * inv,
                         o[m2][n][h2 * 2 + 1] * inv);
            }
        }
    }
}

// ---------------------------------------------------------------------------
// Launch
// ---------------------------------------------------------------------------
extern "C" void kernel_launch(void* const* d_in, const int* in_sizes, int n_in,
                              void* d_out, int out_size)
{
    const float* x      = (const float*)d_in[0];
    const float* qkv_w  = (const float*)d_in[1];
    const float* qkv_b  = (const float*)d_in[2];
    const float* out_w  = (const float*)d_in[3];
    const float* out_b  = (const float*)d_in[4];
    float* out = (float*)d_out;

    __half *qkv_ptr, *ctx_ptr, *xh_ptr, *w1h_ptr, *w2h_ptr;
    cudaGetSymbolAddress((void**)&qkv_ptr, g_qkv_h);
    cudaGetSymbolAddress((void**)&ctx_ptr, g_ctx_h);
    cudaGetSymbolAddress((void**)&xh_ptr, g_xh);
    cudaGetSymbolAddress((void**)&w1h_ptr, g_w1h);
    cudaGetSymbolAddress((void**)&w2h_ptr, g_w2h);

    cudaFuncSetAttribute(gemm_h_kernel<true>,
                         cudaFuncAttributeMaxDynamicSharedMemorySize, GEMM_SMEM);
    cudaFuncSetAttribute(gemm_h_kernel<false>,
                         cudaFuncAttributeMaxDynamicSharedMemorySize, GEMM_SMEM);
    cudaFuncSetAttribute(attn_h_kernel,
                         cudaFuncAttributeMaxDynamicSharedMemorySize, ATT_SMEM);

    // 0) fused fp16 pre-conversion
    cvt_h_all<<<(N4_ALL + 255) / 256, 256>>>(
        (const float4*)x, (uint2*)xh_ptr,
        (const float4*)qkv_w, (uint2*)w1h_ptr,
        (const float4*)out_w, (uint2*)w2h_ptr);

    // 1) QKV projection (fp16 out, q columns pre-scaled by QSCALE)
    gemm_h_kernel<true><<<dim3(QKV_N / BN, M_ / BM), 256, GEMM_SMEM>>>(
        xh_ptr, w1h_ptr, qkv_b, qkv_ptr, M_, QKV_N, C_);

    // 2) causal flash attention (fp16, exp2-domain softmax, ldmatrix)
    attn_h_kernel<<<dim3(H_ * B_, T_ / QB), 128, ATT_SMEM>>>(qkv_ptr, ctx_ptr);

    // 3) output projection (fp16 in, f32 out)
    gemm_h_kernel<false><<<dim3(C_ / BN, M_ / BM), 256, GEMM_SMEM>>>(
        ctx_ptr, w2h_ptr, out_b, out, M_, C_, C_);
}